// round 12
// baseline (speedup 1.0000x reference)
#include <cuda_runtime.h>

#define B_ROWS 8192
#define C_COLS 2048
#define GAMA   0.3f

// Scratch (device globals — allocation is forbidden)
__device__ float    g_t[B_ROWS];    // valid ? pos - GAMA : +3e30 sentinel
__device__ float    g_neg[B_ROWS];  // sigmoid(masked row max)
__device__ unsigned g_ticket;       // monotone across replays; (old+1)%grid==0 -> last

__device__ __forceinline__ float sigmoidf(float v) {
    return 1.0f / (1.0f + __expf(-v));
}

// One fused kernel:
//   phase 1 (all 8192 blocks): per-row masked max -> neg, pos -> t
//   phase 2 (last block only): O(B) closed-form pairwise sum + loss
//
// Pairwise identity: sq_sum = sum_{i valid} sum_{j: neg_j > t_i} (t_i - neg_j)^2.
// When t_i < min_j neg_j the inner condition holds for ALL j, so the inner sum
// is B*t^2 - 2*t*S1 + S2 with S1 = sum neg, S2 = sum neg^2. Rows with
// t_i >= min_neg (none expected for this data, but handled for exactness) fall
// back to an explicit scan over neg. sigmoid > 0 and monotone make the
// masked-max formulation exactly equal to the reference's masked-sigmoid max.
__global__ void __launch_bounds__(256) fused_kernel(
    const float* __restrict__ x, const void* __restrict__ yraw,
    float* __restrict__ out) {

    int row = blockIdx.x;
    const float* xr = x + (size_t)row * C_COLS;

    // ---- label dtype detection (block-uniform, deterministic) ----
    // Read 16 int64 words (128 B — within the buffer even if it's int32 data).
    // int32 labels reinterpreted as int64 carry a random label in the high
    // 32 bits, so "all 16 values in [0,C)" identifies genuine int64.
    const long long* y64 = (const long long*)yraw;
    long long probe = __ldg(&y64[threadIdx.x & 15]);
    bool ok = (probe >= 0) && (probe < (long long)C_COLS);
    bool use64 = __all_sync(0xffffffffu, ok);  // warp-uniform, same all warps

    int yi = use64 ? (int)__ldg(&y64[row]) : __ldg(&((const int*)yraw)[row]);

    // ---- phase 1: masked row max (exclude col yi and col 0) ----
    // x is read-once: stream it (evict-first) to keep L2 clean.
    const float4* xr4 = (const float4*)xr;
    float m = -1e30f;
    #pragma unroll
    for (int v = 0; v < 2; v++) {
        int idx4 = threadIdx.x * 2 + v;
        float4 f = __ldcs(&xr4[idx4]);
        int base = idx4 * 4;
        float a0 = (base + 0 == yi || base == 0) ? -1e30f : f.x;
        float a1 = (base + 1 == yi) ? -1e30f : f.y;
        float a2 = (base + 2 == yi) ? -1e30f : f.z;
        float a3 = (base + 3 == yi) ? -1e30f : f.w;
        m = fmaxf(m, fmaxf(fmaxf(a0, a1), fmaxf(a2, a3)));
    }
    #pragma unroll
    for (int o = 16; o; o >>= 1)
        m = fmaxf(m, __shfl_xor_sync(0xffffffffu, m, o));

    __shared__ float wmax[8];
    __shared__ int s_last;
    if ((threadIdx.x & 31) == 0) wmax[threadIdx.x >> 5] = m;
    __syncthreads();
    if (threadIdx.x == 0) {
        float mm = wmax[0];
        #pragma unroll
        for (int w = 1; w < 8; w++) mm = fmaxf(mm, wmax[w]);
        g_neg[row] = sigmoidf(mm);
        float pos = sigmoidf(__ldg(&xr[yi]));
        g_t[row] = (yi != 0) ? (pos - GAMA) : 3.0e30f;
        __threadfence();  // publish g_neg/g_t before taking the ticket
        unsigned old = atomicAdd(&g_ticket, 1u);
        s_last = ((old + 1u) % (unsigned)gridDim.x) == 0u;
    }
    __syncthreads();
    if (!s_last) return;
    __threadfence();  // acquire side: order subsequent loads after the ticket

    // ---- phase 2 (last block, 256 threads): reduction + loss ----
    const float4* n4 = (const float4*)g_neg;
    const float4* t4 = (const float4*)g_t;

    double S1 = 0.0, S2 = 0.0;
    float  mn = 1e30f;
    int    cnt = 0;
    float  tloc[32];

    #pragma unroll
    for (int k = 0; k < 8; k++) {
        int idx = threadIdx.x + 256 * k;
        float4 n = n4[idx];
        float4 t = t4[idx];
        S1 += (double)n.x + (double)n.y + (double)n.z + (double)n.w;
        S2 += (double)n.x * n.x + (double)n.y * n.y
            + (double)n.z * n.z + (double)n.w * n.w;
        mn = fminf(mn, fminf(fminf(n.x, n.y), fminf(n.z, n.w)));
        tloc[4 * k + 0] = t.x; tloc[4 * k + 1] = t.y;
        tloc[4 * k + 2] = t.z; tloc[4 * k + 3] = t.w;
        cnt += (t.x < 1e29f) + (t.y < 1e29f) + (t.z < 1e29f) + (t.w < 1e29f);
    }

    // block reduce S1, S2 (double), mn (float), cnt (int)
    __shared__ double rs1[8], rs2[8];
    __shared__ float  rmn[8];
    __shared__ int    rcnt[8];
    #pragma unroll
    for (int o = 16; o; o >>= 1) {
        S1  += __shfl_xor_sync(0xffffffffu, S1, o);
        S2  += __shfl_xor_sync(0xffffffffu, S2, o);
        mn   = fminf(mn, __shfl_xor_sync(0xffffffffu, mn, o));
        cnt += __shfl_xor_sync(0xffffffffu, cnt, o);
    }
    int w = threadIdx.x >> 5;
    if ((threadIdx.x & 31) == 0) { rs1[w] = S1; rs2[w] = S2; rmn[w] = mn; rcnt[w] = cnt; }
    __syncthreads();
    double S1a = 0.0, S2a = 0.0; float mna = 1e30f; int cnta = 0;
    #pragma unroll
    for (int i = 0; i < 8; i++) {
        S1a += rs1[i]; S2a += rs2[i];
        mna = fminf(mna, rmn[i]); cnta += rcnt[i];
    }

    // per-row contributions
    double acc = 0.0;
    #pragma unroll
    for (int k = 0; k < 32; k++) {
        float t = tloc[k];
        if (t < 1e29f) {
            if (t < mna) {
                double td = t;
                acc += (double)B_ROWS * td * td - 2.0 * td * S1a + S2a;
            } else {
                // exact fallback: strict margin < 0 only
                double facc = 0.0;
                for (int j = 0; j < B_ROWS; j++) {
                    float d = fminf(t - __ldg(&g_neg[j]), 0.0f);
                    facc += (double)d * d;
                }
                acc += facc;
            }
        }
    }

    // block reduce acc (double)
    __shared__ double racc[8];
    #pragma unroll
    for (int o = 16; o; o >>= 1)
        acc += __shfl_xor_sync(0xffffffffu, acc, o);
    if ((threadIdx.x & 31) == 0) racc[w] = acc;
    __syncthreads();
    if (threadIdx.x == 0) {
        double a = 0.0;
        #pragma unroll
        for (int i = 0; i < 8; i++) a += racc[i];
        out[0] = (float)(a / ((double)cnta + 1.0) / ((double)B_ROWS + 1.0));
    }
}

extern "C" void kernel_launch(void* const* d_in, const int* in_sizes, int n_in,
                              void* d_out, int out_size) {
    const float* x = (const float*)d_in[0];
    const void*  y = d_in[1];
    fused_kernel<<<B_ROWS, 256>>>(x, y, (float*)d_out);
}

// round 16
// speedup vs baseline: 1.4645x; 1.4645x over previous
#include <cuda_runtime.h>

#define B_ROWS 8192
#define C_COLS 2048
#define GAMA   0.3f
#define RPB    8          // rows per block (one warp per row)
#define NBLK   (B_ROWS / RPB)   // 1024

// Scratch (device globals — allocation is forbidden)
__device__ float    g_t[B_ROWS];    // valid ? pos - GAMA : +3e30 sentinel
__device__ float    g_neg[B_ROWS];  // sigmoid(masked row max)
__device__ unsigned g_ticket;       // monotone across replays; (old+1)%grid==0 -> last

__device__ __forceinline__ float sigmoidf(float v) {
    return 1.0f / (1.0f + __expf(-v));
}

// Phase 1: one WARP per row. Each lane owns 16 float4 (lane + 32k stride,
// coalesced). Full unroll lets ptxas front-batch the 16 independent LDG.128
// -> 8 KB in flight per warp (the R12 version had 1 KB -> DRAM at 12%).
// 4 max accumulators break the FMNMX RAW chain.
// Phase 2 (last block): O(B) closed-form pairwise sum, exact min-guarded
// fallback. sigmoid > 0 and monotone make masked-max == reference.
__global__ void __launch_bounds__(256) fused_kernel(
    const float* __restrict__ x, const void* __restrict__ yraw,
    float* __restrict__ out) {

    int wid  = threadIdx.x >> 5;
    int lane = threadIdx.x & 31;
    int row  = blockIdx.x * RPB + wid;
    const float4* xr4 = (const float4*)(x + (size_t)row * C_COLS);

    // ---- label dtype detection (warp-uniform, deterministic) ----
    // 16 int64 words = 128 B, within the buffer even if data is int32.
    // int32 reinterpreted as int64 has a random label in the high word, so
    // "all 16 in [0,C)" identifies genuine int64.
    const long long* y64 = (const long long*)yraw;
    long long probe = __ldg(&y64[lane & 15]);
    bool ok = (probe >= 0) && (probe < (long long)C_COLS);
    bool use64 = __all_sync(0xffffffffu, ok);
    int yi = use64 ? (int)__ldg(&y64[row]) : __ldg(&((const int*)yraw)[row]);

    // ---- phase 1: masked row max (exclude col yi and col 0) ----
    float m0 = -1e30f, m1 = -1e30f, m2 = -1e30f, m3 = -1e30f;
    #pragma unroll
    for (int k = 0; k < 16; k++) {
        int idx4 = lane + 32 * k;
        float4 f = __ldcs(&xr4[idx4]);
        int base = idx4 * 4;
        float a0 = (base + 0 == yi || base == 0) ? -1e30f : f.x;
        float a1 = (base + 1 == yi) ? -1e30f : f.y;
        float a2 = (base + 2 == yi) ? -1e30f : f.z;
        float a3 = (base + 3 == yi) ? -1e30f : f.w;
        if ((k & 3) == 0)      m0 = fmaxf(m0, fmaxf(fmaxf(a0, a1), fmaxf(a2, a3)));
        else if ((k & 3) == 1) m1 = fmaxf(m1, fmaxf(fmaxf(a0, a1), fmaxf(a2, a3)));
        else if ((k & 3) == 2) m2 = fmaxf(m2, fmaxf(fmaxf(a0, a1), fmaxf(a2, a3)));
        else                   m3 = fmaxf(m3, fmaxf(fmaxf(a0, a1), fmaxf(a2, a3)));
    }
    float m = fmaxf(fmaxf(m0, m1), fmaxf(m2, m3));
    #pragma unroll
    for (int o = 16; o; o >>= 1)
        m = fmaxf(m, __shfl_xor_sync(0xffffffffu, m, o));

    if (lane == 0) {
        g_neg[row] = sigmoidf(m);
        float pos = sigmoidf(__ldg(&((const float*)xr4) [yi]));
        g_t[row] = (yi != 0) ? (pos - GAMA) : 3.0e30f;
    }
    __syncthreads();

    __shared__ int s_last;
    if (threadIdx.x == 0) {
        __threadfence();  // publish this block's g_neg/g_t before the ticket
        unsigned old = atomicAdd(&g_ticket, 1u);
        s_last = ((old + 1u) % (unsigned)gridDim.x) == 0u;
    }
    __syncthreads();
    if (!s_last) return;
    __threadfence();  // acquire side

    // ---- phase 2 (last block, 256 threads): reduction + loss ----
    const float4* n4 = (const float4*)g_neg;
    const float4* t4 = (const float4*)g_t;

    double S1 = 0.0, S2 = 0.0;
    float  mn = 1e30f;
    int    cnt = 0;
    float  tloc[32];

    #pragma unroll
    for (int k = 0; k < 8; k++) {
        int idx = threadIdx.x + 256 * k;
        float4 n = n4[idx];
        float4 t = t4[idx];
        S1 += (double)n.x + (double)n.y + (double)n.z + (double)n.w;
        S2 += (double)n.x * n.x + (double)n.y * n.y
            + (double)n.z * n.z + (double)n.w * n.w;
        mn = fminf(mn, fminf(fminf(n.x, n.y), fminf(n.z, n.w)));
        tloc[4 * k + 0] = t.x; tloc[4 * k + 1] = t.y;
        tloc[4 * k + 2] = t.z; tloc[4 * k + 3] = t.w;
        cnt += (t.x < 1e29f) + (t.y < 1e29f) + (t.z < 1e29f) + (t.w < 1e29f);
    }

    __shared__ double rs1[8], rs2[8];
    __shared__ float  rmn[8];
    __shared__ int    rcnt[8];
    #pragma unroll
    for (int o = 16; o; o >>= 1) {
        S1  += __shfl_xor_sync(0xffffffffu, S1, o);
        S2  += __shfl_xor_sync(0xffffffffu, S2, o);
        mn   = fminf(mn, __shfl_xor_sync(0xffffffffu, mn, o));
        cnt += __shfl_xor_sync(0xffffffffu, cnt, o);
    }
    int w = threadIdx.x >> 5;
    if ((threadIdx.x & 31) == 0) { rs1[w] = S1; rs2[w] = S2; rmn[w] = mn; rcnt[w] = cnt; }
    __syncthreads();
    double S1a = 0.0, S2a = 0.0; float mna = 1e30f; int cnta = 0;
    #pragma unroll
    for (int i = 0; i < 8; i++) {
        S1a += rs1[i]; S2a += rs2[i];
        mna = fminf(mna, rmn[i]); cnta += rcnt[i];
    }

    double acc = 0.0;
    #pragma unroll
    for (int k = 0; k < 32; k++) {
        float t = tloc[k];
        if (t < 1e29f) {
            if (t < mna) {
                double td = t;
                acc += (double)B_ROWS * td * td - 2.0 * td * S1a + S2a;
            } else {
                // exact fallback: strict margin < 0 only
                double facc = 0.0;
                for (int j = 0; j < B_ROWS; j++) {
                    float d = fminf(t - __ldg(&g_neg[j]), 0.0f);
                    facc += (double)d * d;
                }
                acc += facc;
            }
        }
    }

    __shared__ double racc[8];
    #pragma unroll
    for (int o = 16; o; o >>= 1)
        acc += __shfl_xor_sync(0xffffffffu, acc, o);
    if ((threadIdx.x & 31) == 0) racc[w] = acc;
    __syncthreads();
    if (threadIdx.x == 0) {
        double a = 0.0;
        #pragma unroll
        for (int i = 0; i < 8; i++) a += racc[i];
        out[0] = (float)(a / ((double)cnta + 1.0) / ((double)B_ROWS + 1.0));
    }
}

extern "C" void kernel_launch(void* const* d_in, const int* in_sizes, int n_in,
                              void* d_out, int out_size) {
    const float* x = (const float*)d_in[0];
    const void*  y = d_in[1];
    fused_kernel<<<NBLK, 256>>>(x, y, (float*)d_out);
}